// round 1
// baseline (speedup 1.0000x reference)
#include <cuda_runtime.h>
#include <math_constants.h>

// ---------------- scratch (static __device__, no allocation) ----------------
#define B_    64
#define C_    256
#define HW_   4096          // 64*64
#define NPLANE (B_*C_)      // 16384
#define NCL   8

__device__ float g_sum[NPLANE];
__device__ float g_min[NPLANE];
__device__ float g_max[NPLANE];
__device__ float g_scale[NPLANE];
__device__ float g_smin[B_];
__device__ float g_smax[B_];
__device__ float g_ss[B_];
__device__ float g_zz[B_];
__device__ float g_inv[B_];

// ---------------- kernel 1: per-(b,c) sum / min / max over 4096 elems -------
// one block per plane, 256 threads, each thread 4 float4 (16 floats)
__global__ __launch_bounds__(256) void k1_reduce(const float* __restrict__ x) {
    const int plane = blockIdx.x;
    const float4* xp = reinterpret_cast<const float4*>(x + (size_t)plane * HW_);

    float s = 0.f, mn = CUDART_INF_F, mx = -CUDART_INF_F;
#pragma unroll
    for (int i = 0; i < 4; ++i) {
        float4 v = xp[threadIdx.x + 256 * i];
        s += (v.x + v.y) + (v.z + v.w);
        mn = fminf(mn, fminf(fminf(v.x, v.y), fminf(v.z, v.w)));
        mx = fmaxf(mx, fmaxf(fmaxf(v.x, v.y), fmaxf(v.z, v.w)));
    }
#pragma unroll
    for (int o = 16; o; o >>= 1) {
        s  += __shfl_xor_sync(0xffffffffu, s, o);
        mn  = fminf(mn, __shfl_xor_sync(0xffffffffu, mn, o));
        mx  = fmaxf(mx, __shfl_xor_sync(0xffffffffu, mx, o));
    }
    __shared__ float sh_s[8], sh_mn[8], sh_mx[8];
    const int lane = threadIdx.x & 31, warp = threadIdx.x >> 5;
    if (lane == 0) { sh_s[warp] = s; sh_mn[warp] = mn; sh_mx[warp] = mx; }
    __syncthreads();
    if (threadIdx.x == 0) {
        float ts = 0.f, tmn = CUDART_INF_F, tmx = -CUDART_INF_F;
#pragma unroll
        for (int w = 0; w < 8; ++w) {
            ts += sh_s[w];
            tmn = fminf(tmn, sh_mn[w]);
            tmx = fmaxf(tmx, sh_mx[w]);
        }
        g_sum[plane] = ts;
        g_min[plane] = tmn;
        g_max[plane] = tmx;
    }
}

// ---------------- kernel 2: SE MLP + per-sample min/max ---------------------
// one block per sample b, 256 threads
__global__ __launch_bounds__(256) void k2_se(const float* __restrict__ w1,
                                             const float* __restrict__ b1,
                                             const float* __restrict__ w2,
                                             const float* __restrict__ b2) {
    const int b = blockIdx.x;
    const int t = threadIdx.x;
    __shared__ float pooled[C_];
    __shared__ float hbuf[64];

    pooled[t] = g_sum[b * C_ + t] * (1.0f / 4096.0f);
    __syncthreads();

    if (t < 64) {
        float acc = b1[t];
        const float* w1r = w1 + t * C_;
#pragma unroll 8
        for (int c = 0; c < C_; ++c) acc += pooled[c] * w1r[c];
        hbuf[t] = fmaxf(acc, 0.0f);
    }
    __syncthreads();

    // v[c] for c = t
    float v = b2[t];
    const float* w2r = w2 + t * 64;
#pragma unroll 8
    for (int s = 0; s < 64; ++s) v += hbuf[s] * w2r[s];
    float sc = fminf(fmaxf(v * (1.0f / 6.0f) + 0.5f, 0.0f), 1.0f);
    g_scale[b * C_ + t] = sc;

    float pmn = sc * g_min[b * C_ + t];   // scale >= 0: min(scale*x) = scale*min(x)
    float pmx = sc * g_max[b * C_ + t];

#pragma unroll
    for (int o = 16; o; o >>= 1) {
        pmn = fminf(pmn, __shfl_xor_sync(0xffffffffu, pmn, o));
        pmx = fmaxf(pmx, __shfl_xor_sync(0xffffffffu, pmx, o));
    }
    __shared__ float sh_mn[8], sh_mx[8];
    const int lane = t & 31, warp = t >> 5;
    if (lane == 0) { sh_mn[warp] = pmn; sh_mx[warp] = pmx; }
    __syncthreads();
    if (t == 0) {
        float tmn = CUDART_INF_F, tmx = -CUDART_INF_F;
#pragma unroll
        for (int w = 0; w < 8; ++w) {
            tmn = fminf(tmn, sh_mn[w]);
            tmx = fmaxf(tmx, sh_mx[w]);
        }
        g_smin[b] = tmn;
        g_smax[b] = tmx;
    }
}

// ---------------- kernel 3: cluster EMA ranges + per-sample (s,z) -----------
__global__ __launch_bounds__(64) void k3_ranges(const float* __restrict__ act_range,
                                                const int* __restrict__ cluster) {
    __shared__ float s_s[NCL], s_z[NCL];
    const int t = threadIdx.x;
    if (t < NCL) {
        float cmin = CUDART_INF_F, cmax = -CUDART_INF_F;
        for (int b = 0; b < B_; ++b) {
            if (cluster[b] == t) {
                cmin = fminf(cmin, g_smin[b]);
                cmax = fmaxf(cmax, g_smax[b]);
            }
        }
        const float SMOOTH = 0.995f;
        const float ONE_M  = 0.005000000000000000104f; // f32(1.0 - 0.995)
        float nmin = act_range[2 * t]     * SMOOTH + cmin * ONE_M;
        float nmax = act_range[2 * t + 1] * SMOOTH + cmax * ONE_M;
        float s = (nmax - nmin) * (1.0f / 255.0f);
        float z = -rintf(nmin / s);
        s_s[t] = s;
        s_z[t] = z;
    }
    __syncthreads();
    if (t < B_) {
        int k = cluster[t];
        g_ss[t]  = s_s[k];
        g_zz[t]  = s_z[k];
        g_inv[t] = 1.0f / s_s[k];
    }
}

// ---------------- kernel 4: streaming scale + fake-quant --------------------
// one block per plane, 256 threads, 4 float4 each
__global__ __launch_bounds__(256) void k4_quant(const float* __restrict__ x,
                                                float* __restrict__ out) {
    const int plane = blockIdx.x;
    const int b = plane >> 8;
    const float sc  = g_scale[plane];
    const float ssv = g_ss[b];
    const float zzv = g_zz[b];
    const float inv = g_inv[b];

    const float4* xp = reinterpret_cast<const float4*>(x   + (size_t)plane * HW_);
    float4*       op = reinterpret_cast<float4*>      (out + (size_t)plane * HW_);

#pragma unroll
    for (int i = 0; i < 4; ++i) {
        float4 v = xp[threadIdx.x + 256 * i];
        float4 r;
        {
            float o = sc * v.x;
            float q = fminf(fmaxf(rintf(fmaf(o, inv, zzv)), 0.0f), 255.0f);
            r.x = (q - zzv) * ssv;
        }
        {
            float o = sc * v.y;
            float q = fminf(fmaxf(rintf(fmaf(o, inv, zzv)), 0.0f), 255.0f);
            r.y = (q - zzv) * ssv;
        }
        {
            float o = sc * v.z;
            float q = fminf(fmaxf(rintf(fmaf(o, inv, zzv)), 0.0f), 255.0f);
            r.z = (q - zzv) * ssv;
        }
        {
            float o = sc * v.w;
            float q = fminf(fmaxf(rintf(fmaf(o, inv, zzv)), 0.0f), 255.0f);
            r.w = (q - zzv) * ssv;
        }
        op[threadIdx.x + 256 * i] = r;
    }
}

// ---------------- launch ----------------------------------------------------
extern "C" void kernel_launch(void* const* d_in, const int* in_sizes, int n_in,
                              void* d_out, int out_size) {
    const float* x          = (const float*)d_in[0];
    const float* w1         = (const float*)d_in[1];
    const float* b1         = (const float*)d_in[2];
    const float* w2         = (const float*)d_in[3];
    const float* b2         = (const float*)d_in[4];
    const float* act_range  = (const float*)d_in[5];
    const int*   cluster    = (const int*)d_in[6];
    float* out = (float*)d_out;

    k1_reduce<<<NPLANE, 256>>>(x);
    k2_se<<<B_, 256>>>(w1, b1, w2, b2);
    k3_ranges<<<1, 64>>>(act_range, cluster);
    k4_quant<<<NPLANE, 256>>>(x, out);
}

// round 4
// speedup vs baseline: 1.0232x; 1.0232x over previous
#include <cuda_runtime.h>
#include <math_constants.h>

#define B_    64
#define C_    256
#define HW_   4096          // 64*64 floats per plane = 1024 float4
#define NPLANE (B_*C_)      // 16384
#define NCL   8

__device__ float g_sum[NPLANE];
__device__ float g_min[NPLANE];
__device__ float g_max[NPLANE];
__device__ float g_scale[NPLANE];
__device__ float g_smin[B_];
__device__ float g_smax[B_];
__device__ float g_ss[B_];
__device__ float g_zz[B_];
__device__ float g_inv[B_];

// ---------------- kernel 1: per-plane sum/min/max, warp-per-plane -----------
// 2048 blocks x 256 threads; each warp owns one plane.
// Plane = 4096 floats = 1024 float4 -> each lane reads 32 float4.
__global__ __launch_bounds__(256) void k1_reduce(const float* __restrict__ x) {
    const int warp  = threadIdx.x >> 5;
    const int lane  = threadIdx.x & 31;
    const int plane = blockIdx.x * 8 + warp;

    const float4* xp = reinterpret_cast<const float4*>(x + (size_t)plane * HW_);

    float s = 0.f, mn = CUDART_INF_F, mx = -CUDART_INF_F;
#pragma unroll 8
    for (int i = 0; i < 32; ++i) {          // 32 * 32 lanes = 1024 float4 ✓
        float4 v = xp[lane + 32 * i];
        s += (v.x + v.y) + (v.z + v.w);
        mn = fminf(mn, fminf(fminf(v.x, v.y), fminf(v.z, v.w)));
        mx = fmaxf(mx, fmaxf(fmaxf(v.x, v.y), fmaxf(v.z, v.w)));
    }
#pragma unroll
    for (int o = 16; o; o >>= 1) {
        s  += __shfl_xor_sync(0xffffffffu, s, o);
        mn  = fminf(mn, __shfl_xor_sync(0xffffffffu, mn, o));
        mx  = fmaxf(mx, __shfl_xor_sync(0xffffffffu, mx, o));
    }
    if (lane == 0) {
        g_sum[plane] = s;
        g_min[plane] = mn;
        g_max[plane] = mx;
    }
}

// ---------------- kernel 2: SE MLP + per-sample min/max ---------------------
__global__ __launch_bounds__(256) void k2_se(const float* __restrict__ w1,
                                             const float* __restrict__ b1,
                                             const float* __restrict__ w2,
                                             const float* __restrict__ b2) {
    const int b = blockIdx.x;
    const int t = threadIdx.x;
    __shared__ float pooled[C_];
    __shared__ float hbuf[64];

    pooled[t] = g_sum[b * C_ + t] * (1.0f / 4096.0f);
    __syncthreads();

    if (t < 64) {
        float acc = b1[t];
        const float* w1r = w1 + t * C_;
#pragma unroll 8
        for (int c = 0; c < C_; ++c) acc += pooled[c] * w1r[c];
        hbuf[t] = fmaxf(acc, 0.0f);
    }
    __syncthreads();

    float v = b2[t];
    const float* w2r = w2 + t * 64;
#pragma unroll 8
    for (int s = 0; s < 64; ++s) v += hbuf[s] * w2r[s];
    float sc = fminf(fmaxf(v * (1.0f / 6.0f) + 0.5f, 0.0f), 1.0f);
    g_scale[b * C_ + t] = sc;

    float pmn = sc * g_min[b * C_ + t];   // scale >= 0: min(scale*x) = scale*min(x)
    float pmx = sc * g_max[b * C_ + t];

#pragma unroll
    for (int o = 16; o; o >>= 1) {
        pmn = fminf(pmn, __shfl_xor_sync(0xffffffffu, pmn, o));
        pmx = fmaxf(pmx, __shfl_xor_sync(0xffffffffu, pmx, o));
    }
    __shared__ float sh_mn[8], sh_mx[8];
    const int lane = t & 31, warp = t >> 5;
    if (lane == 0) { sh_mn[warp] = pmn; sh_mx[warp] = pmx; }
    __syncthreads();
    if (t == 0) {
        float tmn = CUDART_INF_F, tmx = -CUDART_INF_F;
#pragma unroll
        for (int w = 0; w < 8; ++w) {
            tmn = fminf(tmn, sh_mn[w]);
            tmx = fmaxf(tmx, sh_mx[w]);
        }
        g_smin[b] = tmn;
        g_smax[b] = tmx;
    }
}

// ---------------- kernel 3: cluster EMA ranges + per-sample (s,z) -----------
__global__ __launch_bounds__(64) void k3_ranges(const float* __restrict__ act_range,
                                                const int* __restrict__ cluster) {
    __shared__ float s_s[NCL], s_z[NCL];
    const int t = threadIdx.x;
    if (t < NCL) {
        float cmin = CUDART_INF_F, cmax = -CUDART_INF_F;
        for (int b = 0; b < B_; ++b) {
            if (cluster[b] == t) {
                cmin = fminf(cmin, g_smin[b]);
                cmax = fmaxf(cmax, g_smax[b]);
            }
        }
        const float SMOOTH = 0.995f;
        const float ONE_M  = 0.005f;
        float nmin = act_range[2 * t]     * SMOOTH + cmin * ONE_M;
        float nmax = act_range[2 * t + 1] * SMOOTH + cmax * ONE_M;
        float s = (nmax - nmin) * (1.0f / 255.0f);
        float z = -rintf(nmin / s);
        s_s[t] = s;
        s_z[t] = z;
    }
    __syncthreads();
    if (t < B_) {
        int k = cluster[t];
        g_ss[t]  = s_s[k];
        g_zz[t]  = s_z[k];
        g_inv[t] = 1.0f / s_s[k];
    }
}

// ---------------- kernel 4: streaming scale + fake-quant --------------------
// Reverse plane order: k1 read planes ascending, so high planes are freshest
// in L2 (~126MB). k4's first wave hits those. Streaming loads/stores keep the
// output write-allocate traffic from evicting useful x lines.
__global__ __launch_bounds__(256) void k4_quant(const float* __restrict__ x,
                                                float* __restrict__ out) {
    const int plane = (NPLANE - 1) - blockIdx.x;
    const int b = plane >> 8;
    const float sc  = g_scale[plane];
    const float ssv = g_ss[b];
    const float zzv = g_zz[b];
    const float inv = g_inv[b];

    const float4* xp = reinterpret_cast<const float4*>(x   + (size_t)plane * HW_);
    float4*       op = reinterpret_cast<float4*>      (out + (size_t)plane * HW_);

#pragma unroll
    for (int i = 0; i < 4; ++i) {
        float4 v = __ldcs(&xp[threadIdx.x + 256 * i]);
        float4 r;
        {
            float o = sc * v.x;
            float q = fminf(fmaxf(rintf(fmaf(o, inv, zzv)), 0.0f), 255.0f);
            r.x = (q - zzv) * ssv;
        }
        {
            float o = sc * v.y;
            float q = fminf(fmaxf(rintf(fmaf(o, inv, zzv)), 0.0f), 255.0f);
            r.y = (q - zzv) * ssv;
        }
        {
            float o = sc * v.z;
            float q = fminf(fmaxf(rintf(fmaf(o, inv, zzv)), 0.0f), 255.0f);
            r.z = (q - zzv) * ssv;
        }
        {
            float o = sc * v.w;
            float q = fminf(fmaxf(rintf(fmaf(o, inv, zzv)), 0.0f), 255.0f);
            r.w = (q - zzv) * ssv;
        }
        __stcs(&op[threadIdx.x + 256 * i], r);
    }
}

// ---------------- launch ----------------------------------------------------
extern "C" void kernel_launch(void* const* d_in, const int* in_sizes, int n_in,
                              void* d_out, int out_size) {
    const float* x          = (const float*)d_in[0];
    const float* w1         = (const float*)d_in[1];
    const float* b1         = (const float*)d_in[2];
    const float* w2         = (const float*)d_in[3];
    const float* b2         = (const float*)d_in[4];
    const float* act_range  = (const float*)d_in[5];
    const int*   cluster    = (const int*)d_in[6];
    float* out = (float*)d_out;

    k1_reduce<<<NPLANE / 8, 256>>>(x);
    k2_se<<<B_, 256>>>(w1, b1, w2, b2);
    k3_ranges<<<1, 64>>>(act_range, cluster);
    k4_quant<<<NPLANE, 256>>>(x, out);
}